// round 5
// baseline (speedup 1.0000x reference)
#include <cuda_runtime.h>
#include <math.h>

// Problem constants
#define BB 256      // batch
#define OO 1024     // output dim
#define HH 2048     // hidden (2*H)
#define SS 12       // encoder seq len

// Scratch (no allocation allowed -> __device__ globals)
__device__ float g_attnw[BB * SS];       // softmax attention weights [B,S]
__device__ float g_attnA[BB * HH];       // attn_applied [B,2H]
__device__ float g_xin[BB * OO];         // relu(comb) [B,O]
__device__ float g_gates[BB * 4 * HH];   // LSTM gates scratch [B,4*2H] (reused for both layers)

// ---------------------------------------------------------------------------
// Kernel 1: attention logits + softmax.
// One block per batch row. logits[s] = [x0|h0[0]] . attn_W[s] + attn_b[s]
// ---------------------------------------------------------------------------
__global__ void attn_softmax_kernel(const float* __restrict__ x0,
                                    const float* __restrict__ h00,
                                    const float* __restrict__ aW,
                                    const float* __restrict__ ab,
                                    float* __restrict__ attnw)
{
    const int b = blockIdx.x;
    const int t = threadIdx.x;          // 256 threads
    float part[SS];
#pragma unroll
    for (int s = 0; s < SS; s++) part[s] = 0.f;

    for (int k = t; k < OO; k += 256) {
        float a = x0[b * OO + k];
#pragma unroll
        for (int s = 0; s < SS; s++) part[s] += a * aW[s * (OO + HH) + k];
    }
    for (int k = t; k < HH; k += 256) {
        float a = h00[b * HH + k];
#pragma unroll
        for (int s = 0; s < SS; s++) part[s] += a * aW[s * (OO + HH) + OO + k];
    }

    // warp reduce each of the 12 partials
#pragma unroll
    for (int s = 0; s < SS; s++)
#pragma unroll
        for (int off = 16; off > 0; off >>= 1)
            part[s] += __shfl_down_sync(0xFFFFFFFFu, part[s], off);

    __shared__ float wred[SS][8];
    __shared__ float logits[SS];
    const int warp = t >> 5, lane = t & 31;
    if (lane == 0)
#pragma unroll
        for (int s = 0; s < SS; s++) wred[s][warp] = part[s];
    __syncthreads();

    if (t < SS) {
        float v = ab[t];
#pragma unroll
        for (int w = 0; w < 8; w++) v += wred[t][w];
        logits[t] = v;
    }
    __syncthreads();

    if (t == 0) {
        float mx = logits[0];
#pragma unroll
        for (int s = 1; s < SS; s++) mx = fmaxf(mx, logits[s]);
        float e[SS], sum = 0.f;
#pragma unroll
        for (int s = 0; s < SS; s++) { e[s] = expf(logits[s] - mx); sum += e[s]; }
        float inv = 1.f / sum;
#pragma unroll
        for (int s = 0; s < SS; s++) attnw[b * SS + s] = e[s] * inv;
    }
}

// ---------------------------------------------------------------------------
// Kernel 2: attn_applied[b,h] = sum_s w[b,s] * enc[s,b,h]
// ---------------------------------------------------------------------------
__global__ void attn_apply_kernel(const float* __restrict__ attnw,
                                  const float* __restrict__ enc,
                                  float* __restrict__ out)
{
    const int b = blockIdx.y;
    const int h = blockIdx.x * blockDim.x + threadIdx.x;
    __shared__ float w[SS];
    if (threadIdx.x < SS) w[threadIdx.x] = attnw[b * SS + threadIdx.x];
    __syncthreads();
    float s = 0.f;
#pragma unroll
    for (int si = 0; si < SS; si++)
        s += w[si] * enc[((size_t)si * BB + b) * HH + h];
    out[(size_t)b * HH + h] = s;
}

// ---------------------------------------------------------------------------
// Generic fused-K tiled GEMM:
//   C[m,n] = act( A1[m,:K1] . W1[n,:K1](ldw1) + A2[m,:K2] . W2[n,:K2](ldw2)
//                 + bias1[n] + bias2[n] )
// A1/A2 row strides are K1/K2 (contiguous). M,N,K multiples of tile sizes.
// ---------------------------------------------------------------------------
template <int BM, int BN, int TM, int TN>
__global__ void __launch_bounds__((BM / TM) * (BN / TN))
gemm2_kernel(float* __restrict__ C, int N,
             const float* __restrict__ A1, int K1,
             const float* __restrict__ W1, int ldw1,
             const float* __restrict__ A2, int K2,
             const float* __restrict__ W2, int ldw2,
             const float* __restrict__ bias1,
             const float* __restrict__ bias2,
             int act)
{
    constexpr int BK = 16;
    constexpr int THREADS = (BM / TM) * (BN / TN);
    constexpr int A_LD = BM * BK / (4 * THREADS);   // float4 loads per thread
    constexpr int W_LD = BN * BK / (4 * THREADS);

    __shared__ __align__(16) float As[BK][BM + 4];
    __shared__ __align__(16) float Ws[BK][BN + 4];

    const int t  = threadIdx.x;
    const int m0 = blockIdx.y * BM;
    const int n0 = blockIdx.x * BN;
    const int tx = t % (BN / TN);
    const int ty = t / (BN / TN);
    const int Kt = K1 + K2;

    float4 rA[A_LD], rW[W_LD];

    auto loadT = [&](int k0) {
#pragma unroll
        for (int i = 0; i < A_LD; i++) {
            int idx = t + i * THREADS;
            int row = idx >> 2, cg = idx & 3;      // BK/4 == 4 float4 per row
            const float* p = (k0 < K1)
                ? A1 + (size_t)(m0 + row) * K1 + (k0 + 4 * cg)
                : A2 + (size_t)(m0 + row) * K2 + (k0 - K1 + 4 * cg);
            rA[i] = *(const float4*)p;
        }
#pragma unroll
        for (int i = 0; i < W_LD; i++) {
            int idx = t + i * THREADS;
            int row = idx >> 2, cg = idx & 3;
            const float* p = (k0 < K1)
                ? W1 + (size_t)(n0 + row) * ldw1 + (k0 + 4 * cg)
                : W2 + (size_t)(n0 + row) * ldw2 + (k0 - K1 + 4 * cg);
            rW[i] = *(const float4*)p;
        }
    };
    auto storeT = [&]() {
#pragma unroll
        for (int i = 0; i < A_LD; i++) {
            int idx = t + i * THREADS;
            int row = idx >> 2, cg = idx & 3;
            As[4 * cg + 0][row] = rA[i].x;
            As[4 * cg + 1][row] = rA[i].y;
            As[4 * cg + 2][row] = rA[i].z;
            As[4 * cg + 3][row] = rA[i].w;
        }
#pragma unroll
        for (int i = 0; i < W_LD; i++) {
            int idx = t + i * THREADS;
            int row = idx >> 2, cg = idx & 3;
            Ws[4 * cg + 0][row] = rW[i].x;
            Ws[4 * cg + 1][row] = rW[i].y;
            Ws[4 * cg + 2][row] = rW[i].z;
            Ws[4 * cg + 3][row] = rW[i].w;
        }
    };

    float acc[TM][TN];
#pragma unroll
    for (int i = 0; i < TM; i++)
#pragma unroll
        for (int j = 0; j < TN; j++) acc[i][j] = 0.f;

    loadT(0);
    storeT();
    __syncthreads();

    for (int k0 = 0; k0 < Kt; k0 += BK) {
        const bool more = (k0 + BK) < Kt;
        if (more) loadT(k0 + BK);       // prefetch next tile into registers
#pragma unroll
        for (int kk = 0; kk < BK; kk++) {
            float a[TM], b[TN];
#pragma unroll
            for (int i = 0; i < TM; i += 4) {
                float4 v = *(const float4*)&As[kk][ty * TM + i];
                a[i] = v.x; a[i + 1] = v.y; a[i + 2] = v.z; a[i + 3] = v.w;
            }
#pragma unroll
            for (int j = 0; j < TN; j += 4) {
                float4 v = *(const float4*)&Ws[kk][tx * TN + j];
                b[j] = v.x; b[j + 1] = v.y; b[j + 2] = v.z; b[j + 3] = v.w;
            }
#pragma unroll
            for (int i = 0; i < TM; i++)
#pragma unroll
                for (int j = 0; j < TN; j++)
                    acc[i][j] = fmaf(a[i], b[j], acc[i][j]);
        }
        __syncthreads();
        if (more) { storeT(); __syncthreads(); }
    }

#pragma unroll
    for (int j = 0; j < TN; j++) {
        const int n = n0 + tx * TN + j;
        float bv = 0.f;
        if (bias1) bv += bias1[n];
        if (bias2) bv += bias2[n];
#pragma unroll
        for (int i = 0; i < TM; i++) {
            const int m = m0 + ty * TM + i;
            float v = acc[i][j] + bv;
            if (act) v = fmaxf(v, 0.f);
            C[(size_t)m * N + n] = v;
        }
    }
}

// ---------------------------------------------------------------------------
// LSTM cell elementwise: gates [B,4*HH] in (i,f,g,o) chunks
// ---------------------------------------------------------------------------
__global__ void lstm_cell_kernel(const float* __restrict__ gates,
                                 const float* __restrict__ c_prev,
                                 float* __restrict__ h_out,
                                 float* __restrict__ c_out)
{
    const int idx = blockIdx.x * blockDim.x + threadIdx.x;  // [0, B*HH)
    const int b = idx >> 11;        // / HH
    const int h = idx & (HH - 1);
    const float* g = gates + (size_t)b * 4 * HH + h;
    const float gi = g[0];
    const float gf = g[HH];
    const float gg = g[2 * HH];
    const float go = g[3 * HH];
    const float si = 1.f / (1.f + expf(-gi));
    const float sf = 1.f / (1.f + expf(-gf));
    const float so = 1.f / (1.f + expf(-go));
    const float cn = sf * c_prev[idx] + si * tanhf(gg);
    c_out[idx] = cn;
    h_out[idx] = so * tanhf(cn);
}

// ---------------------------------------------------------------------------
// Launch
// ---------------------------------------------------------------------------
extern "C" void kernel_launch(void* const* d_in, const int* in_sizes, int n_in,
                              void* d_out, int out_size)
{
    const float* x0   = (const float*)d_in[0];   // (1,B,O)
    const float* h0   = (const float*)d_in[1];   // (L,B,2H)
    const float* c0   = (const float*)d_in[2];
    const float* enc  = (const float*)d_in[3];   // (S,B,2H)
    const float* aW   = (const float*)d_in[4];   // (S, 2H+O)
    const float* ab   = (const float*)d_in[5];
    const float* cW   = (const float*)d_in[6];   // (O, 2H+O)
    const float* cb   = (const float*)d_in[7];
    const float* Wih0 = (const float*)d_in[8];   // (4*2H, O)
    const float* Whh0 = (const float*)d_in[9];   // (4*2H, 2H)
    const float* bih0 = (const float*)d_in[10];
    const float* bhh0 = (const float*)d_in[11];
    const float* Wih1 = (const float*)d_in[12];  // (4*2H, 2H)
    const float* Whh1 = (const float*)d_in[13];
    const float* bih1 = (const float*)d_in[14];
    const float* bhh1 = (const float*)d_in[15];
    const float* oW   = (const float*)d_in[16];  // (O, 2H)
    const float* ob   = (const float*)d_in[17];
    float* out = (float*)d_out;

    float *attnw, *attnA, *xin, *gates;
    cudaGetSymbolAddress((void**)&attnw, g_attnw);
    cudaGetSymbolAddress((void**)&attnA, g_attnA);
    cudaGetSymbolAddress((void**)&xin,   g_xin);
    cudaGetSymbolAddress((void**)&gates, g_gates);

    const size_t BH = (size_t)BB * HH;           // 524288
    const float* h00 = h0;
    const float* h01 = h0 + BH;
    const float* c00 = c0;
    const float* c01 = c0 + BH;

    // Output layout: [prediction (B*O) | h_new (2*B*2H) | c_new (2*B*2H)]
    float* pred = out;
    float* h1 = out + (size_t)BB * OO;
    float* h2 = h1 + BH;
    float* c1 = out + (size_t)BB * OO + 2 * BH;
    float* c2 = c1 + BH;

    // 1) attention softmax weights
    attn_softmax_kernel<<<BB, 256>>>(x0, h00, aW, ab, attnw);

    // 2) attn_applied
    attn_apply_kernel<<<dim3(HH / 256, BB), 256>>>(attnw, enc, attnA);

    // 3) xin = relu([x0|attnA] @ comb_W.T + comb_b)   (M=256, N=1024, K=3072)
    gemm2_kernel<64, 64, 4, 4><<<dim3(OO / 64, BB / 64), 256>>>(
        xin, OO,
        x0, OO, cW, OO + HH,
        attnA, HH, cW + OO, OO + HH,
        cb, nullptr, 1);

    // 4) gates0 = xin@Wih0.T + h0[0]@Whh0.T + bih0 + bhh0  (N=8192, K=3072)
    gemm2_kernel<64, 128, 4, 8><<<dim3(4 * HH / 128, BB / 64), 256>>>(
        gates, 4 * HH,
        xin, OO, Wih0, OO,
        h00, HH, Whh0, HH,
        bih0, bhh0, 0);

    // 5) LSTM cell layer 0 -> h1, c1 (written straight into d_out)
    lstm_cell_kernel<<<(unsigned)(BH / 256), 256>>>(gates, c00, h1, c1);

    // 6) gates1 = h1@Wih1.T + h0[1]@Whh1.T + bih1 + bhh1  (N=8192, K=4096)
    gemm2_kernel<64, 128, 4, 8><<<dim3(4 * HH / 128, BB / 64), 256>>>(
        gates, 4 * HH,
        h1, HH, Wih1, HH,
        h01, HH, Whh1, HH,
        bih1, bhh1, 0);

    // 7) LSTM cell layer 1 -> h2, c2
    lstm_cell_kernel<<<(unsigned)(BH / 256), 256>>>(gates, c01, h2, c2);

    // 8) prediction = h2 @ out_W.T + out_b  (M=256, N=1024, K=2048)
    gemm2_kernel<64, 64, 4, 4><<<dim3(OO / 64, BB / 64), 256>>>(
        pred, OO,
        h2, HH, oW, HH,
        nullptr, 0, nullptr, 0,
        ob, nullptr, 0);
}

// round 7
// speedup vs baseline: 3.0696x; 3.0696x over previous
#include <cuda_runtime.h>
#include <cuda_bf16.h>
#include <cstdint>
#include <math.h>

// Problem constants
#define BB 256      // batch (M of all GEMMs)
#define OO 1024     // output dim
#define HH 2048     // hidden (2*H)
#define SS 12       // encoder seq len

// Scratch (no allocation allowed -> __device__ globals)
__device__ float g_attnw[BB * SS];
__device__ float g_attnA[BB * HH];
__device__ float g_xin[BB * OO];
__device__ float g_gates[BB * 4 * HH];

// ---------------------------------------------------------------------------
// Helpers
// ---------------------------------------------------------------------------
__device__ __forceinline__ uint32_t smem_u32(const void* p) {
    uint32_t a;
    asm("{ .reg .u64 t; cvta.to.shared.u64 t, %1; cvt.u32.u64 %0, t; }"
        : "=r"(a) : "l"(p));
    return a;
}

__device__ __forceinline__ void ldm4(uint32_t* r, uint32_t a) {
    asm volatile("ldmatrix.sync.aligned.m8n8.x4.shared.b16 {%0,%1,%2,%3}, [%4];"
                 : "=r"(r[0]), "=r"(r[1]), "=r"(r[2]), "=r"(r[3]) : "r"(a));
}

__device__ __forceinline__ void mma16816(float* d, const uint32_t* a,
                                         const uint32_t* b) {
    asm volatile(
        "mma.sync.aligned.m16n8k16.row.col.f32.bf16.bf16.f32 "
        "{%0,%1,%2,%3}, {%4,%5,%6,%7}, {%8,%9}, {%0,%1,%2,%3};"
        : "+f"(d[0]), "+f"(d[1]), "+f"(d[2]), "+f"(d[3])
        : "r"(a[0]), "r"(a[1]), "r"(a[2]), "r"(a[3]), "r"(b[0]), "r"(b[1]));
}

// fp32 -> (hi, lo) bf16x2 pairs for 4 consecutive K elements
__device__ __forceinline__ void split_bf(float4 v, uint2& hi, uint2& lo) {
    __nv_bfloat162 h01 = __floats2bfloat162_rn(v.x, v.y);
    __nv_bfloat162 h23 = __floats2bfloat162_rn(v.z, v.w);
    float2 f01 = __bfloat1622float2(h01);
    float2 f23 = __bfloat1622float2(h23);
    __nv_bfloat162 l01 = __floats2bfloat162_rn(v.x - f01.x, v.y - f01.y);
    __nv_bfloat162 l23 = __floats2bfloat162_rn(v.z - f23.x, v.w - f23.y);
    hi.x = *reinterpret_cast<uint32_t*>(&h01);
    hi.y = *reinterpret_cast<uint32_t*>(&h23);
    lo.x = *reinterpret_cast<uint32_t*>(&l01);
    lo.y = *reinterpret_cast<uint32_t*>(&l23);
}

// ===========================================================================
// HMMA fused-K GEMM:
//   C[M, N] = act( A1[M,:K1].W1^T + A2[M,:K2].W2^T + bias1 + bias2 )
// A, W row-major K-contiguous. K1, K2 multiples of 32. bf16 hi/lo 3-term
// split with fp32 accumulate for ~1e-6 accuracy.
// Tiles: CTA BMxBN, warps WMSxWNS, warp tile (BM/WMS)x(BN/WNS), BK=32.
// ===========================================================================
template <int BM, int BN, int WMS, int WNS>
__global__ void __launch_bounds__(WMS * WNS * 32, 1)
hmma_gemm(float* __restrict__ C, int N,
          const float* __restrict__ A1, int K1,
          const float* __restrict__ W1, int ldw1,
          const float* __restrict__ A2, int K2,
          const float* __restrict__ W2, int ldw2,
          const float* __restrict__ bias1,
          const float* __restrict__ bias2, int act)
{
    constexpr int THREADS = WMS * WNS * 32;
    constexpr int WM = BM / WMS;            // warp tile M (64 or 32)
    constexpr int WN = BN / WNS;            // warp tile N (32)
    constexpr int MT = WM / 16;             // m16 tiles per warp
    constexpr int NT = WN / 8;              // n8 tiles per warp (4)
    constexpr int ROWB = 80;                // 64B payload + 16B skew (conflict-free ldmatrix)
    constexpr int TA = BM * ROWB;
    constexpr int TB = BN * ROWB;
    constexpr int STAGE = 2 * TA + 2 * TB;  // Ahi, Alo, Bhi, Blo
    constexpr int ALD = BM * 32 / (4 * THREADS);
    constexpr int BLD = BN * 32 / (4 * THREADS);

    extern __shared__ char smc[];
    const uint32_t sb = smem_u32(smc);

    const int tid = threadIdx.x;
    const int wid = tid >> 5, lane = tid & 31;
    const int wm = wid / WNS, wn = wid % WNS;
    const int m0 = blockIdx.y * BM;
    const int n0 = blockIdx.x * BN;
    const int Kt = K1 + K2;
    const int S = Kt >> 5;

    float4 rA[ALD], rB[BLD];

    auto load_regs = [&](int kg) {
        const float* pa; const float* pw; int lda, ldw;
        if (kg < K1) { pa = A1 + kg; lda = K1; pw = W1 + kg; ldw = ldw1; }
        else { pa = A2 + (kg - K1); lda = K2; pw = W2 + (kg - K1); ldw = ldw2; }
#pragma unroll
        for (int i = 0; i < ALD; i++) {
            int idx = tid + i * THREADS;
            int r = idx >> 3, c = idx & 7;      // 8 float4 per 32-float row
            rA[i] = *(const float4*)(pa + (size_t)(m0 + r) * lda + c * 4);
        }
#pragma unroll
        for (int i = 0; i < BLD; i++) {
            int idx = tid + i * THREADS;
            int r = idx >> 3, c = idx & 7;
            rB[i] = *(const float4*)(pw + (size_t)(n0 + r) * ldw + c * 4);
        }
    };
    auto store_smem = [&](int buf) {
        char* bp = smc + buf * STAGE;
#pragma unroll
        for (int i = 0; i < ALD; i++) {
            int idx = tid + i * THREADS;
            int r = idx >> 3, c = idx & 7;
            int off = r * ROWB + c * 8;
            uint2 h, l;
            split_bf(rA[i], h, l);
            *(uint2*)(bp + off) = h;
            *(uint2*)(bp + TA + off) = l;
        }
#pragma unroll
        for (int i = 0; i < BLD; i++) {
            int idx = tid + i * THREADS;
            int r = idx >> 3, c = idx & 7;
            int off = r * ROWB + c * 8;
            uint2 h, l;
            split_bf(rB[i], h, l);
            *(uint2*)(bp + 2 * TA + off) = h;
            *(uint2*)(bp + 2 * TA + TB + off) = l;
        }
    };

    float acc[MT][NT][4];
#pragma unroll
    for (int i = 0; i < MT; i++)
#pragma unroll
        for (int j = 0; j < NT; j++)
#pragma unroll
            for (int k = 0; k < 4; k++) acc[i][j][k] = 0.f;

    // ldmatrix per-thread base offsets (lane -> 8x8 matrix row/col-half)
    const int lrow = (lane & 7) + ((lane >> 3) & 1) * 8;
    const int lcol = ((lane >> 4) & 1) * 16;             // byte offset of k-half
    const uint32_t aoff = (uint32_t)((wm * WM + lrow) * ROWB + lcol);
    const uint32_t boff = (uint32_t)((wn * WN + lrow) * ROWB + lcol);

    load_regs(0);
    store_smem(0);
    __syncthreads();

    for (int s = 0; s < S; s++) {
        const int buf = s & 1;
        if (s + 1 < S) load_regs((s + 1) << 5);   // LDG overlaps MMA below

        const uint32_t stb = sb + buf * STAGE;
#pragma unroll
        for (int ks = 0; ks < 2; ks++) {
            uint32_t ah[MT][4], al[MT][4];
#pragma unroll
            for (int i = 0; i < MT; i++) {
                uint32_t ad = stb + aoff + i * 16 * ROWB + ks * 32;
                ldm4(ah[i], ad);
                ldm4(al[i], ad + TA);
            }
            uint32_t bh[NT][2], bl[NT][2];
#pragma unroll
            for (int jj = 0; jj < NT / 2; jj++) {
                uint32_t bd = stb + 2 * TA + boff + jj * 16 * ROWB + ks * 32;
                uint32_t t[4];
                ldm4(t, bd);
                bh[2 * jj][0] = t[0]; bh[2 * jj][1] = t[2];
                bh[2 * jj + 1][0] = t[1]; bh[2 * jj + 1][1] = t[3];
                ldm4(t, bd + TB);
                bl[2 * jj][0] = t[0]; bl[2 * jj][1] = t[2];
                bl[2 * jj + 1][0] = t[1]; bl[2 * jj + 1][1] = t[3];
            }
#pragma unroll
            for (int i = 0; i < MT; i++)
#pragma unroll
                for (int j = 0; j < NT; j++) {
                    mma16816(acc[i][j], ah[i], bh[j]);   // hi*hi
                    mma16816(acc[i][j], ah[i], bl[j]);   // hi*lo
                    mma16816(acc[i][j], al[i], bh[j]);   // lo*hi
                }
        }
        __syncthreads();
        if (s + 1 < S) {
            store_smem((s + 1) & 1);
            __syncthreads();
        }
    }

    // Epilogue: fp32 accumulators -> C with bias (+ optional ReLU)
#pragma unroll
    for (int j = 0; j < NT; j++) {
        const int col = n0 + wn * WN + j * 8 + (lane & 3) * 2;
        float b0 = 0.f, b1 = 0.f;
        if (bias1) { b0 = bias1[col]; b1 = bias1[col + 1]; }
        if (bias2) { b0 += bias2[col]; b1 += bias2[col + 1]; }
#pragma unroll
        for (int i = 0; i < MT; i++) {
            const int row = m0 + wm * WM + i * 16 + (lane >> 2);
            float2 v0 = make_float2(acc[i][j][0] + b0, acc[i][j][1] + b1);
            float2 v1 = make_float2(acc[i][j][2] + b0, acc[i][j][3] + b1);
            if (act) {
                v0.x = fmaxf(v0.x, 0.f); v0.y = fmaxf(v0.y, 0.f);
                v1.x = fmaxf(v1.x, 0.f); v1.y = fmaxf(v1.y, 0.f);
            }
            *(float2*)(C + (size_t)row * N + col) = v0;
            *(float2*)(C + (size_t)(row + 8) * N + col) = v1;
        }
    }
}

// Shared-memory sizes for the two instantiations
#define BIG_SMEM  (2 * (2 * 128 * 80 + 2 * 128 * 80))   // 81920
#define SMALL_SMEM (2 * (2 * 64 * 80 + 2 * 64 * 80))    // 40960

// ===========================================================================
// Attention softmax (one block per batch row)
// ===========================================================================
__global__ void attn_softmax_kernel(const float* __restrict__ x0,
                                    const float* __restrict__ h00,
                                    const float* __restrict__ aW,
                                    const float* __restrict__ ab,
                                    float* __restrict__ attnw)
{
    const int b = blockIdx.x;
    const int t = threadIdx.x;          // 256 threads
    float part[SS];
#pragma unroll
    for (int s = 0; s < SS; s++) part[s] = 0.f;

    for (int k = t; k < OO; k += 256) {
        float a = x0[b * OO + k];
#pragma unroll
        for (int s = 0; s < SS; s++) part[s] += a * aW[s * (OO + HH) + k];
    }
    for (int k = t; k < HH; k += 256) {
        float a = h00[b * HH + k];
#pragma unroll
        for (int s = 0; s < SS; s++) part[s] += a * aW[s * (OO + HH) + OO + k];
    }
#pragma unroll
    for (int s = 0; s < SS; s++)
#pragma unroll
        for (int off = 16; off > 0; off >>= 1)
            part[s] += __shfl_down_sync(0xFFFFFFFFu, part[s], off);

    __shared__ float wred[SS][8];
    __shared__ float logits[SS];
    const int warp = t >> 5, lane = t & 31;
    if (lane == 0)
#pragma unroll
        for (int s = 0; s < SS; s++) wred[s][warp] = part[s];
    __syncthreads();

    if (t < SS) {
        float v = ab[t];
#pragma unroll
        for (int w = 0; w < 8; w++) v += wred[t][w];
        logits[t] = v;
    }
    __syncthreads();

    if (t == 0) {
        float mx = logits[0];
#pragma unroll
        for (int s = 1; s < SS; s++) mx = fmaxf(mx, logits[s]);
        float e[SS], sum = 0.f;
#pragma unroll
        for (int s = 0; s < SS; s++) { e[s] = expf(logits[s] - mx); sum += e[s]; }
        float inv = 1.f / sum;
#pragma unroll
        for (int s = 0; s < SS; s++) attnw[b * SS + s] = e[s] * inv;
    }
}

// ===========================================================================
// attn_applied[b,h] = sum_s w[b,s] * enc[s,b,h]
// ===========================================================================
__global__ void attn_apply_kernel(const float* __restrict__ attnw,
                                  const float* __restrict__ enc,
                                  float* __restrict__ out)
{
    const int b = blockIdx.y;
    const int h = blockIdx.x * blockDim.x + threadIdx.x;
    __shared__ float w[SS];
    if (threadIdx.x < SS) w[threadIdx.x] = attnw[b * SS + threadIdx.x];
    __syncthreads();
    float s = 0.f;
#pragma unroll
    for (int si = 0; si < SS; si++)
        s += w[si] * enc[((size_t)si * BB + b) * HH + h];
    out[(size_t)b * HH + h] = s;
}

// ===========================================================================
// LSTM cell elementwise
// ===========================================================================
__global__ void lstm_cell_kernel(const float* __restrict__ gates,
                                 const float* __restrict__ c_prev,
                                 float* __restrict__ h_out,
                                 float* __restrict__ c_out)
{
    const int idx = blockIdx.x * blockDim.x + threadIdx.x;
    const int b = idx >> 11;
    const int h = idx & (HH - 1);
    const float* g = gates + (size_t)b * 4 * HH + h;
    const float gi = g[0];
    const float gf = g[HH];
    const float gg = g[2 * HH];
    const float go = g[3 * HH];
    const float si = 1.f / (1.f + expf(-gi));
    const float sf = 1.f / (1.f + expf(-gf));
    const float so = 1.f / (1.f + expf(-go));
    const float cn = sf * c_prev[idx] + si * tanhf(gg);
    c_out[idx] = cn;
    h_out[idx] = so * tanhf(cn);
}

// ===========================================================================
// Launch
// ===========================================================================
extern "C" void kernel_launch(void* const* d_in, const int* in_sizes, int n_in,
                              void* d_out, int out_size)
{
    const float* x0   = (const float*)d_in[0];
    const float* h0   = (const float*)d_in[1];
    const float* c0   = (const float*)d_in[2];
    const float* enc  = (const float*)d_in[3];
    const float* aW   = (const float*)d_in[4];
    const float* ab   = (const float*)d_in[5];
    const float* cW   = (const float*)d_in[6];
    const float* cb   = (const float*)d_in[7];
    const float* Wih0 = (const float*)d_in[8];
    const float* Whh0 = (const float*)d_in[9];
    const float* bih0 = (const float*)d_in[10];
    const float* bhh0 = (const float*)d_in[11];
    const float* Wih1 = (const float*)d_in[12];
    const float* Whh1 = (const float*)d_in[13];
    const float* bih1 = (const float*)d_in[14];
    const float* bhh1 = (const float*)d_in[15];
    const float* oW   = (const float*)d_in[16];
    const float* ob   = (const float*)d_in[17];
    float* out = (float*)d_out;

    float *attnw, *attnA, *xin, *gates;
    cudaGetSymbolAddress((void**)&attnw, g_attnw);
    cudaGetSymbolAddress((void**)&attnA, g_attnA);
    cudaGetSymbolAddress((void**)&xin,   g_xin);
    cudaGetSymbolAddress((void**)&gates, g_gates);

    cudaFuncSetAttribute(hmma_gemm<128, 128, 2, 4>,
                         cudaFuncAttributeMaxDynamicSharedMemorySize, BIG_SMEM);
    cudaFuncSetAttribute(hmma_gemm<64, 64, 2, 2>,
                         cudaFuncAttributeMaxDynamicSharedMemorySize, SMALL_SMEM);

    const size_t BH = (size_t)BB * HH;
    const float* h00 = h0;
    const float* h01 = h0 + BH;
    const float* c00 = c0;
    const float* c01 = c0 + BH;

    float* pred = out;
    float* h1 = out + (size_t)BB * OO;
    float* h2 = h1 + BH;
    float* c1 = out + (size_t)BB * OO + 2 * BH;
    float* c2 = c1 + BH;

    // 1) attention softmax weights
    attn_softmax_kernel<<<BB, 256>>>(x0, h00, aW, ab, attnw);

    // 2) attn_applied
    attn_apply_kernel<<<dim3(HH / 256, BB), 256>>>(attnw, enc, attnA);

    // 3) xin = relu([x0|attnA] @ comb_W.T + comb_b)  (N=1024, K=1024+2048)
    hmma_gemm<64, 64, 2, 2><<<dim3(OO / 64, BB / 64), 128, SMALL_SMEM>>>(
        xin, OO, x0, OO, cW, OO + HH, attnA, HH, cW + OO, OO + HH, cb, nullptr, 1);

    // 4) gates0 = xin@Wih0.T + h0[0]@Whh0.T + biases  (N=8192, K=1024+2048)
    hmma_gemm<128, 128, 2, 4><<<dim3(4 * HH / 128, BB / 128), 256, BIG_SMEM>>>(
        gates, 4 * HH, xin, OO, Wih0, OO, h00, HH, Whh0, HH, bih0, bhh0, 0);

    // 5) LSTM cell layer 0 -> h1, c1
    lstm_cell_kernel<<<(unsigned)(BH / 256), 256>>>(gates, c00, h1, c1);

    // 6) gates1 = h1@Wih1.T + h0[1]@Whh1.T + biases  (N=8192, K=2048+2048)
    hmma_gemm<128, 128, 2, 4><<<dim3(4 * HH / 128, BB / 128), 256, BIG_SMEM>>>(
        gates, 4 * HH, h1, HH, Wih1, HH, h01, HH, Whh1, HH, bih1, bhh1, 0);

    // 7) LSTM cell layer 1 -> h2, c2
    lstm_cell_kernel<<<(unsigned)(BH / 256), 256>>>(gates, c01, h2, c2);

    // 8) prediction = h2 @ out_W.T + out_b  (N=1024, K=2048)
    hmma_gemm<64, 64, 2, 2><<<dim3(OO / 64, BB / 64), 128, SMALL_SMEM>>>(
        pred, OO, h2, HH, oW, HH, nullptr, 0, nullptr, 0, ob, nullptr, 0);
}

// round 9
// speedup vs baseline: 3.6361x; 1.1845x over previous
#include <cuda_runtime.h>
#include <cuda_bf16.h>
#include <cstdint>
#include <math.h>

// Problem constants
#define BB 256      // batch (M of all GEMMs)
#define OO 1024     // output dim
#define HH 2048     // hidden (2*H)
#define SS 12       // encoder seq len

// Scratch (no allocation allowed -> __device__ globals)
__device__ float g_attnw[BB * SS];
__device__ float g_attnA[BB * HH];
__device__ float g_xin[BB * OO];
__device__ float g_gates[BB * 4 * HH];
__device__ float g_part[4 * BB * OO];    // split-K partials (<= 4 splits x 256 x 1024)

// ---------------------------------------------------------------------------
// Helpers
// ---------------------------------------------------------------------------
__device__ __forceinline__ uint32_t smem_u32(const void* p) {
    uint32_t a;
    asm("{ .reg .u64 t; cvta.to.shared.u64 t, %1; cvt.u32.u64 %0, t; }"
        : "=r"(a) : "l"(p));
    return a;
}

__device__ __forceinline__ void ldm4(uint32_t* r, uint32_t a) {
    asm volatile("ldmatrix.sync.aligned.m8n8.x4.shared.b16 {%0,%1,%2,%3}, [%4];"
                 : "=r"(r[0]), "=r"(r[1]), "=r"(r[2]), "=r"(r[3]) : "r"(a));
}

__device__ __forceinline__ void mma16816(float* d, const uint32_t* a,
                                         const uint32_t* b) {
    asm volatile(
        "mma.sync.aligned.m16n8k16.row.col.f32.bf16.bf16.f32 "
        "{%0,%1,%2,%3}, {%4,%5,%6,%7}, {%8,%9}, {%0,%1,%2,%3};"
        : "+f"(d[0]), "+f"(d[1]), "+f"(d[2]), "+f"(d[3])
        : "r"(a[0]), "r"(a[1]), "r"(a[2]), "r"(a[3]), "r"(b[0]), "r"(b[1]));
}

// fp32 -> (hi, lo) bf16x2 pairs for 4 consecutive K elements
__device__ __forceinline__ void split_bf(float4 v, uint2& hi, uint2& lo) {
    __nv_bfloat162 h01 = __floats2bfloat162_rn(v.x, v.y);
    __nv_bfloat162 h23 = __floats2bfloat162_rn(v.z, v.w);
    float2 f01 = __bfloat1622float2(h01);
    float2 f23 = __bfloat1622float2(h23);
    __nv_bfloat162 l01 = __floats2bfloat162_rn(v.x - f01.x, v.y - f01.y);
    __nv_bfloat162 l23 = __floats2bfloat162_rn(v.z - f23.x, v.w - f23.y);
    hi.x = *reinterpret_cast<uint32_t*>(&h01);
    hi.y = *reinterpret_cast<uint32_t*>(&h23);
    lo.x = *reinterpret_cast<uint32_t*>(&l01);
    lo.y = *reinterpret_cast<uint32_t*>(&l23);
}

// ===========================================================================
// HMMA fused-K GEMM (+ optional split-K):
//   C[M, N] = act( A1[M,:K1].W1^T + A2[M,:K2].W2^T + bias1 + bias2 )
// bf16 hi/lo 3-term split, fp32 accumulate. BK=32.
// 3-buffer smem ring, one barrier per K-stage.
// If part != nullptr: blockIdx.z selects a K-chunk of s_per stages; raw
// partial sums are written to part[z][m][n] (no bias / act).
// ===========================================================================
template <int BM, int BN, int WMS, int WNS>
__global__ void __launch_bounds__(WMS * WNS * 32, 1)
hmma_gemm(float* __restrict__ C, int N,
          const float* __restrict__ A1, int K1,
          const float* __restrict__ W1, int ldw1,
          const float* __restrict__ A2, int K2,
          const float* __restrict__ W2, int ldw2,
          const float* __restrict__ bias1,
          const float* __restrict__ bias2, int act,
          int s_per, float* __restrict__ part)
{
    constexpr int THREADS = WMS * WNS * 32;
    constexpr int WM = BM / WMS;
    constexpr int WN = BN / WNS;
    constexpr int MT = WM / 16;
    constexpr int NT = WN / 8;
    constexpr int ROWB = 80;                // 64B payload + 16B skew
    constexpr int TA = BM * ROWB;
    constexpr int TB = BN * ROWB;
    constexpr int STAGE = 2 * TA + 2 * TB;  // Ahi, Alo, Bhi, Blo
    constexpr int ALD = BM * 32 / (4 * THREADS);
    constexpr int BLD = BN * 32 / (4 * THREADS);

    extern __shared__ char smc[];
    const uint32_t sb = smem_u32(smc);

    const int tid = threadIdx.x;
    const int wid = tid >> 5, lane = tid & 31;
    const int wm = wid / WNS, wn = wid % WNS;
    const int m0 = blockIdx.y * BM;
    const int n0 = blockIdx.x * BN;
    const int Kt = K1 + K2;
    const int Stot = Kt >> 5;
    const int s0 = part ? (int)blockIdx.z * s_per : 0;
    const int s1 = part ? min(s0 + s_per, Stot) : Stot;

    float4 rA[ALD], rB[BLD];

    auto load_regs = [&](int kg) {
        const float* pa; const float* pw; int lda, ldw;
        if (kg < K1) { pa = A1 + kg; lda = K1; pw = W1 + kg; ldw = ldw1; }
        else { pa = A2 + (kg - K1); lda = K2; pw = W2 + (kg - K1); ldw = ldw2; }
#pragma unroll
        for (int i = 0; i < ALD; i++) {
            int idx = tid + i * THREADS;
            int r = idx >> 3, c = idx & 7;
            rA[i] = *(const float4*)(pa + (size_t)(m0 + r) * lda + c * 4);
        }
#pragma unroll
        for (int i = 0; i < BLD; i++) {
            int idx = tid + i * THREADS;
            int r = idx >> 3, c = idx & 7;
            rB[i] = *(const float4*)(pw + (size_t)(n0 + r) * ldw + c * 4);
        }
    };
    auto store_smem = [&](int buf) {
        char* bp = smc + buf * STAGE;
#pragma unroll
        for (int i = 0; i < ALD; i++) {
            int idx = tid + i * THREADS;
            int r = idx >> 3, c = idx & 7;
            int off = r * ROWB + c * 8;
            uint2 h, l;
            split_bf(rA[i], h, l);
            *(uint2*)(bp + off) = h;
            *(uint2*)(bp + TA + off) = l;
        }
#pragma unroll
        for (int i = 0; i < BLD; i++) {
            int idx = tid + i * THREADS;
            int r = idx >> 3, c = idx & 7;
            int off = r * ROWB + c * 8;
            uint2 h, l;
            split_bf(rB[i], h, l);
            *(uint2*)(bp + 2 * TA + off) = h;
            *(uint2*)(bp + 2 * TA + TB + off) = l;
        }
    };

    float acc[MT][NT][4];
#pragma unroll
    for (int i = 0; i < MT; i++)
#pragma unroll
        for (int j = 0; j < NT; j++)
#pragma unroll
            for (int k = 0; k < 4; k++) acc[i][j][k] = 0.f;

    // ldmatrix per-thread base offsets
    const int lrow = (lane & 7) + ((lane >> 3) & 1) * 8;
    const int lcol = ((lane >> 4) & 1) * 16;
    const uint32_t aoff = sb + (uint32_t)((wm * WM + lrow) * ROWB + lcol);
    const uint32_t boff = sb + (uint32_t)(2 * TA + (wn * WN + lrow) * ROWB + lcol);

    // Prologue: stage s0 -> buf 0
    load_regs(s0 << 5);
    store_smem(0);
    __syncthreads();

    int cur = 0;
    for (int s = s0; s < s1; s++) {
        const bool more = (s + 1) < s1;
        if (more) load_regs((s + 1) << 5);

        const uint32_t stb = (uint32_t)(cur * STAGE);
#pragma unroll
        for (int ks = 0; ks < 2; ks++) {
            uint32_t ah[MT][4], al[MT][4];
#pragma unroll
            for (int i = 0; i < MT; i++) {
                uint32_t ad = aoff + stb + i * 16 * ROWB + ks * 32;
                ldm4(ah[i], ad);
                ldm4(al[i], ad + TA);
            }
            uint32_t bh[NT][2], bl[NT][2];
#pragma unroll
            for (int jj = 0; jj < NT / 2; jj++) {
                uint32_t bd = boff + stb + jj * 16 * ROWB + ks * 32;
                uint32_t t[4];
                ldm4(t, bd);
                bh[2 * jj][0] = t[0]; bh[2 * jj][1] = t[2];
                bh[2 * jj + 1][0] = t[1]; bh[2 * jj + 1][1] = t[3];
                ldm4(t, bd + TB);
                bl[2 * jj][0] = t[0]; bl[2 * jj][1] = t[2];
                bl[2 * jj + 1][0] = t[1]; bl[2 * jj + 1][1] = t[3];
            }
#pragma unroll
            for (int i = 0; i < MT; i++)
#pragma unroll
                for (int j = 0; j < NT; j++) {
                    mma16816(acc[i][j], ah[i], bh[j]);   // hi*hi
                    mma16816(acc[i][j], ah[i], bl[j]);   // hi*lo
                    mma16816(acc[i][j], al[i], bh[j]);   // lo*hi
                }
        }
        if (more) {
            cur = (cur == 2) ? 0 : cur + 1;
            store_smem(cur);
        }
        __syncthreads();
    }

    // Epilogue
    if (part) {
        float* dst = part + (size_t)blockIdx.z * (size_t)(gridDim.y * BM) * N;
#pragma unroll
        for (int j = 0; j < NT; j++) {
            const int col = n0 + wn * WN + j * 8 + (lane & 3) * 2;
#pragma unroll
            for (int i = 0; i < MT; i++) {
                const int row = m0 + wm * WM + i * 16 + (lane >> 2);
                *(float2*)(dst + (size_t)row * N + col) =
                    make_float2(acc[i][j][0], acc[i][j][1]);
                *(float2*)(dst + (size_t)(row + 8) * N + col) =
                    make_float2(acc[i][j][2], acc[i][j][3]);
            }
        }
    } else {
#pragma unroll
        for (int j = 0; j < NT; j++) {
            const int col = n0 + wn * WN + j * 8 + (lane & 3) * 2;
            float b0 = 0.f, b1 = 0.f;
            if (bias1) { b0 = bias1[col]; b1 = bias1[col + 1]; }
            if (bias2) { b0 += bias2[col]; b1 += bias2[col + 1]; }
#pragma unroll
            for (int i = 0; i < MT; i++) {
                const int row = m0 + wm * WM + i * 16 + (lane >> 2);
                float2 v0 = make_float2(acc[i][j][0] + b0, acc[i][j][1] + b1);
                float2 v1 = make_float2(acc[i][j][2] + b0, acc[i][j][3] + b1);
                if (act) {
                    v0.x = fmaxf(v0.x, 0.f); v0.y = fmaxf(v0.y, 0.f);
                    v1.x = fmaxf(v1.x, 0.f); v1.y = fmaxf(v1.y, 0.f);
                }
                *(float2*)(C + (size_t)row * N + col) = v0;
                *(float2*)(C + (size_t)(row + 8) * N + col) = v1;
            }
        }
    }
}

// Split-K reduce: C[m,n] = act( sum_z part[z][m][n] + bias[n] )
__global__ void splitk_reduce(const float* __restrict__ part,
                              float* __restrict__ C,
                              const float* __restrict__ bias,
                              int MN, int N, int act)
{
    const int i = (blockIdx.x * 256 + threadIdx.x) * 4;
    if (i >= MN) return;
    float4 s = *(const float4*)(part + i);
#pragma unroll
    for (int z = 1; z < 4; z++) {
        float4 p = *(const float4*)(part + (size_t)z * MN + i);
        s.x += p.x; s.y += p.y; s.z += p.z; s.w += p.w;
    }
    const int col = i & (N - 1);
    if (bias) {
        float4 b = *(const float4*)(bias + col);
        s.x += b.x; s.y += b.y; s.z += b.z; s.w += b.w;
    }
    if (act) {
        s.x = fmaxf(s.x, 0.f); s.y = fmaxf(s.y, 0.f);
        s.z = fmaxf(s.z, 0.f); s.w = fmaxf(s.w, 0.f);
    }
    *(float4*)(C + i) = s;
}

// Shared-memory sizes (3 ring buffers)
#define BIG_SMEM   (3 * (2 * 128 * 80 + 2 * 128 * 80))   // 122880
#define SMALL_SMEM (3 * (2 * 128 * 80 + 2 * 64 * 80))    // 92160

// ===========================================================================
// Attention softmax (one block per batch row)
// ===========================================================================
__global__ void attn_softmax_kernel(const float* __restrict__ x0,
                                    const float* __restrict__ h00,
                                    const float* __restrict__ aW,
                                    const float* __restrict__ ab,
                                    float* __restrict__ attnw)
{
    const int b = blockIdx.x;
    const int t = threadIdx.x;          // 256 threads
    float part[SS];
#pragma unroll
    for (int s = 0; s < SS; s++) part[s] = 0.f;

    for (int k = t; k < OO; k += 256) {
        float a = x0[b * OO + k];
#pragma unroll
        for (int s = 0; s < SS; s++) part[s] += a * aW[s * (OO + HH) + k];
    }
    for (int k = t; k < HH; k += 256) {
        float a = h00[b * HH + k];
#pragma unroll
        for (int s = 0; s < SS; s++) part[s] += a * aW[s * (OO + HH) + OO + k];
    }
#pragma unroll
    for (int s = 0; s < SS; s++)
#pragma unroll
        for (int off = 16; off > 0; off >>= 1)
            part[s] += __shfl_down_sync(0xFFFFFFFFu, part[s], off);

    __shared__ float wred[SS][8];
    __shared__ float logits[SS];
    const int warp = t >> 5, lane = t & 31;
    if (lane == 0)
#pragma unroll
        for (int s = 0; s < SS; s++) wred[s][warp] = part[s];
    __syncthreads();

    if (t < SS) {
        float v = ab[t];
#pragma unroll
        for (int w = 0; w < 8; w++) v += wred[t][w];
        logits[t] = v;
    }
    __syncthreads();

    if (t == 0) {
        float mx = logits[0];
#pragma unroll
        for (int s = 1; s < SS; s++) mx = fmaxf(mx, logits[s]);
        float e[SS], sum = 0.f;
#pragma unroll
        for (int s = 0; s < SS; s++) { e[s] = expf(logits[s] - mx); sum += e[s]; }
        float inv = 1.f / sum;
#pragma unroll
        for (int s = 0; s < SS; s++) attnw[b * SS + s] = e[s] * inv;
    }
}

// ===========================================================================
// attn_applied[b,h] = sum_s w[b,s] * enc[s,b,h]
// ===========================================================================
__global__ void attn_apply_kernel(const float* __restrict__ attnw,
                                  const float* __restrict__ enc,
                                  float* __restrict__ out)
{
    const int b = blockIdx.y;
    const int h = blockIdx.x * blockDim.x + threadIdx.x;
    __shared__ float w[SS];
    if (threadIdx.x < SS) w[threadIdx.x] = attnw[b * SS + threadIdx.x];
    __syncthreads();
    float s = 0.f;
#pragma unroll
    for (int si = 0; si < SS; si++)
        s += w[si] * enc[((size_t)si * BB + b) * HH + h];
    out[(size_t)b * HH + h] = s;
}

// ===========================================================================
// LSTM cell elementwise
// ===========================================================================
__global__ void lstm_cell_kernel(const float* __restrict__ gates,
                                 const float* __restrict__ c_prev,
                                 float* __restrict__ h_out,
                                 float* __restrict__ c_out)
{
    const int idx = blockIdx.x * blockDim.x + threadIdx.x;
    const int b = idx >> 11;
    const int h = idx & (HH - 1);
    const float* g = gates + (size_t)b * 4 * HH + h;
    const float gi = g[0];
    const float gf = g[HH];
    const float gg = g[2 * HH];
    const float go = g[3 * HH];
    const float si = 1.f / (1.f + expf(-gi));
    const float sf = 1.f / (1.f + expf(-gf));
    const float so = 1.f / (1.f + expf(-go));
    const float cn = sf * c_prev[idx] + si * tanhf(gg);
    c_out[idx] = cn;
    h_out[idx] = so * tanhf(cn);
}

// ===========================================================================
// Launch
// ===========================================================================
extern "C" void kernel_launch(void* const* d_in, const int* in_sizes, int n_in,
                              void* d_out, int out_size)
{
    const float* x0   = (const float*)d_in[0];
    const float* h0   = (const float*)d_in[1];
    const float* c0   = (const float*)d_in[2];
    const float* enc  = (const float*)d_in[3];
    const float* aW   = (const float*)d_in[4];
    const float* ab   = (const float*)d_in[5];
    const float* cW   = (const float*)d_in[6];
    const float* cb   = (const float*)d_in[7];
    const float* Wih0 = (const float*)d_in[8];
    const float* Whh0 = (const float*)d_in[9];
    const float* bih0 = (const float*)d_in[10];
    const float* bhh0 = (const float*)d_in[11];
    const float* Wih1 = (const float*)d_in[12];
    const float* Whh1 = (const float*)d_in[13];
    const float* bih1 = (const float*)d_in[14];
    const float* bhh1 = (const float*)d_in[15];
    const float* oW   = (const float*)d_in[16];
    const float* ob   = (const float*)d_in[17];
    float* out = (float*)d_out;

    float *attnw, *attnA, *xin, *gates, *partbuf;
    cudaGetSymbolAddress((void**)&attnw, g_attnw);
    cudaGetSymbolAddress((void**)&attnA, g_attnA);
    cudaGetSymbolAddress((void**)&xin,   g_xin);
    cudaGetSymbolAddress((void**)&gates, g_gates);
    cudaGetSymbolAddress((void**)&partbuf, g_part);

    cudaFuncSetAttribute(hmma_gemm<128, 128, 2, 4>,
                         cudaFuncAttributeMaxDynamicSharedMemorySize, BIG_SMEM);
    cudaFuncSetAttribute(hmma_gemm<128, 64, 2, 2>,
                         cudaFuncAttributeMaxDynamicSharedMemorySize, SMALL_SMEM);

    const size_t BH = (size_t)BB * HH;
    const float* h00 = h0;
    const float* h01 = h0 + BH;
    const float* c00 = c0;
    const float* c01 = c0 + BH;

    float* pred = out;
    float* h1 = out + (size_t)BB * OO;
    float* h2 = h1 + BH;
    float* c1 = out + (size_t)BB * OO + 2 * BH;
    float* c2 = c1 + BH;

    // 1) attention softmax weights
    attn_softmax_kernel<<<BB, 256>>>(x0, h00, aW, ab, attnw);

    // 2) attn_applied
    attn_apply_kernel<<<dim3(HH / 256, BB), 256>>>(attnw, enc, attnA);

    // 3) xin = relu([x0|attnA] @ comb_W.T + comb_b)  (N=1024, K=3072, split-K=4)
    hmma_gemm<128, 64, 2, 2><<<dim3(OO / 64, BB / 128, 4), 128, SMALL_SMEM>>>(
        nullptr, OO, x0, OO, cW, OO + HH, attnA, HH, cW + OO, OO + HH,
        nullptr, nullptr, 0, /*s_per=*/24, partbuf);
    splitk_reduce<<<BB * OO / (4 * 256), 256>>>(partbuf, xin, cb, BB * OO, OO, 1);

    // 4) gates0 = xin@Wih0.T + h0[0]@Whh0.T + biases  (N=8192, K=3072)
    hmma_gemm<128, 128, 2, 4><<<dim3(4 * HH / 128, BB / 128), 256, BIG_SMEM>>>(
        gates, 4 * HH, xin, OO, Wih0, OO, h00, HH, Whh0, HH,
        bih0, bhh0, 0, 0, nullptr);

    // 5) LSTM cell layer 0 -> h1, c1
    lstm_cell_kernel<<<(unsigned)(BH / 256), 256>>>(gates, c00, h1, c1);

    // 6) gates1 = h1@Wih1.T + h0[1]@Whh1.T + biases  (N=8192, K=4096)
    hmma_gemm<128, 128, 2, 4><<<dim3(4 * HH / 128, BB / 128), 256, BIG_SMEM>>>(
        gates, 4 * HH, h1, HH, Wih1, HH, h01, HH, Whh1, HH,
        bih1, bhh1, 0, 0, nullptr);

    // 7) LSTM cell layer 1 -> h2, c2
    lstm_cell_kernel<<<(unsigned)(BH / 256), 256>>>(gates, c01, h2, c2);

    // 8) prediction = h2 @ out_W.T + out_b  (N=1024, K=2048, split-K=4)
    hmma_gemm<128, 64, 2, 2><<<dim3(OO / 64, BB / 128, 4), 128, SMALL_SMEM>>>(
        nullptr, OO, h2, HH, oW, HH, nullptr, 0, nullptr, 0,
        nullptr, nullptr, 0, /*s_per=*/16, partbuf);
    splitk_reduce<<<BB * OO / (4 * 256), 256>>>(partbuf, pred, ob, BB * OO, OO, 0);
}